// round 4
// baseline (speedup 1.0000x reference)
#include <cuda_runtime.h>
#include <cuda_bf16.h>

// Problem constants
#define LSEQ  1024
#define BATCH 16
#define DIN   1024
#define NOUT  512
#define NLAY  4
#define MROWS (LSEQ*BATCH)   // 16384
#define KDIM  1024
#define NDIM  3072           // 6 * NOUT
#define NCH   16             // scan chunks
#define CH    64             // steps per chunk
#define NCHAIN 16384         // 2*B*NOUT

// Scratch (device globals: allocation-free)
__device__ float g_x0[MROWS * DIN];        // fp32 x (ping)
__device__ float g_x1[MROWS * DIN];        // fp32 x (pong)
__device__ float g_xa[MROWS * DIN];        // tf32 copy of GEMM A operand
__device__ float g_u [MROWS * NDIM];       // gate activations
__device__ float g_wt[NLAY * KDIM * NDIM]; // tf32-converted weights
__device__ float g_F [NCH * NCHAIN];       // chunk decay products
__device__ float g_C [NCH * NCHAIN];       // chunk affine constants
__device__ float g_ce[NCH * NCHAIN];       // chunk entry c values

__device__ __forceinline__ unsigned f2tf32(float x) {
    unsigned r;
    asm("cvt.rna.tf32.f32 %0, %1;" : "=r"(r) : "f"(x));
    return r;
}
__device__ __forceinline__ float tanh_fast(float x) {
    float y;
    asm("tanh.approx.f32 %0, %1;" : "=f"(y) : "f"(x));
    return y;
}
__device__ __forceinline__ void mma_tf32(float c[4],
                                         unsigned a0, unsigned a1, unsigned a2, unsigned a3,
                                         unsigned b0, unsigned b1) {
    asm volatile(
        "mma.sync.aligned.m16n8k8.row.col.f32.tf32.tf32.f32 "
        "{%0,%1,%2,%3}, {%4,%5,%6,%7}, {%8,%9}, {%0,%1,%2,%3};"
        : "+f"(c[0]), "+f"(c[1]), "+f"(c[2]), "+f"(c[3])
        : "r"(a0), "r"(a1), "r"(a2), "r"(a3), "r"(b0), "r"(b1));
}

// ---------------------------------------------------------------------------
// Weight pre-convert: fp32 -> tf32 (stored as float), once per run
// ---------------------------------------------------------------------------
__global__ void wconv_kernel(const float* __restrict__ W, float* __restrict__ Wt) {
    int e = blockIdx.x * blockDim.x + threadIdx.x;
    float4 v = reinterpret_cast<const float4*>(W)[e];
    v.x = __uint_as_float(f2tf32(v.x));
    v.y = __uint_as_float(f2tf32(v.y));
    v.z = __uint_as_float(f2tf32(v.z));
    v.w = __uint_as_float(f2tf32(v.w));
    reinterpret_cast<float4*>(Wt)[e] = v;
}

// ---------------------------------------------------------------------------
// Embedding gather: fp32 x + tf32 copy for GEMM A
// ---------------------------------------------------------------------------
__global__ void gather_kernel(const int* __restrict__ tok,
                              const float* __restrict__ emb,
                              float* __restrict__ out,
                              float* __restrict__ outA) {
    int e = blockIdx.x * blockDim.x + threadIdx.x;
    int row = e >> 8;
    int d4  = e & 255;
    int t = tok[row];
    float4 v = reinterpret_cast<const float4*>(emb + (size_t)t * DIN)[d4];
    reinterpret_cast<float4*>(out)[e] = v;
    v.x = __uint_as_float(f2tf32(v.x));
    v.y = __uint_as_float(f2tf32(v.y));
    v.z = __uint_as_float(f2tf32(v.z));
    v.w = __uint_as_float(f2tf32(v.w));
    reinterpret_cast<float4*>(outA)[e] = v;
}

// ---------------------------------------------------------------------------
// TF32 GEMM: U = X(M,K)*W(K,N), 128x128 block, BK=16, 128 threads,
// 2x2 warps of 64x64 tiles. Inputs already tf32-rounded -> no cvt in loop.
// Fused bias+sigmoid on gate columns.
// A smem: pair layout  As[buf][s*1028 + r*8 + j*2 + half] = A[r][8s+j+4*half]
// B smem: plain [k][n], stride 136 (conflict-free)
// ---------------------------------------------------------------------------
#define A_PLANE 1028
#define B_STRIDE 136

__global__ void __launch_bounds__(128, 2)
gemm_tf32_kernel(const float* __restrict__ A,
                 const float* __restrict__ W,
                 const float* __restrict__ bias,
                 float* __restrict__ U) {
    __shared__ float As[2][2 * A_PLANE];
    __shared__ float Bs[2][16 * B_STRIDE];

    const int tid  = threadIdx.x;
    const int lane = tid & 31;
    const int warp = tid >> 5;
    const int wm = warp >> 1;        // 0..1
    const int wn = warp & 1;         // 0..1
    const int rowBase = blockIdx.y * 128;
    const int colBase = blockIdx.x * 128;

    // A staging: one row per thread, 16 k per iter (4 float4)
    const float* Ag = A + (size_t)(rowBase + tid) * KDIM;
    // B staging: k = tid>>3 (0..15), n = (tid&7)*4 + e*32
    const int bk = tid >> 3;
    const int bn = (tid & 7) * 4;
    const float* Bg = W + (size_t)bk * NDIM + colBase + bn;

    float4 pa[4], pb[4];
    #pragma unroll
    for (int e = 0; e < 4; e++) {
        pa[e] = *reinterpret_cast<const float4*>(Ag + e * 4);
        pb[e] = *reinterpret_cast<const float4*>(Bg + e * 32);
    }

    float acc[4][8][4];
    #pragma unroll
    for (int mf = 0; mf < 4; mf++)
        #pragma unroll
        for (int nf = 0; nf < 8; nf++)
            #pragma unroll
            for (int e = 0; e < 4; e++) acc[mf][nf][e] = 0.f;

    auto stage = [&](int buf) {
        float* ap = &As[buf][tid * 8];
        // plane 0: k0..7  -> {k0,k4,k1,k5} {k2,k6,k3,k7}
        *reinterpret_cast<float4*>(ap) = make_float4(pa[0].x, pa[1].x, pa[0].y, pa[1].y);
        *reinterpret_cast<float4*>(ap + 4) = make_float4(pa[0].z, pa[1].z, pa[0].w, pa[1].w);
        // plane 1: k8..15
        *reinterpret_cast<float4*>(ap + A_PLANE) = make_float4(pa[2].x, pa[3].x, pa[2].y, pa[3].y);
        *reinterpret_cast<float4*>(ap + A_PLANE + 4) = make_float4(pa[2].z, pa[3].z, pa[2].w, pa[3].w);
        #pragma unroll
        for (int e = 0; e < 4; e++)
            *reinterpret_cast<float4*>(&Bs[buf][bk * B_STRIDE + bn + e * 32]) = pb[e];
    };

    stage(0);
    __syncthreads();

    const int q = lane >> 2;
    const int j = lane & 3;
    int buf = 0;

    for (int it = 0; it < 64; it++) {
        if (it < 63) {
            const float* Ag2 = Ag + (it + 1) * 16;
            const float* Bg2 = Bg + (size_t)(it + 1) * 16 * NDIM;
            #pragma unroll
            for (int e = 0; e < 4; e++) {
                pa[e] = *reinterpret_cast<const float4*>(Ag2 + e * 4);
                pb[e] = *reinterpret_cast<const float4*>(Bg2 + e * 32);
            }
        }

        #pragma unroll
        for (int s = 0; s < 2; s++) {
            float2 alo[4], ahi[4];
            #pragma unroll
            for (int mf = 0; mf < 4; mf++) {
                int r = wm * 64 + mf * 16 + q;
                alo[mf] = *reinterpret_cast<const float2*>(
                    &As[buf][s * A_PLANE + r * 8 + j * 2]);
                ahi[mf] = *reinterpret_cast<const float2*>(
                    &As[buf][s * A_PLANE + (r + 8) * 8 + j * 2]);
            }
            float b0[8], b1[8];
            #pragma unroll
            for (int nf = 0; nf < 8; nf++) {
                int n = wn * 64 + nf * 8 + q;
                b0[nf] = Bs[buf][(s * 8 + j) * B_STRIDE + n];
                b1[nf] = Bs[buf][(s * 8 + j + 4) * B_STRIDE + n];
            }
            #pragma unroll
            for (int mf = 0; mf < 4; mf++)
                #pragma unroll
                for (int nf = 0; nf < 8; nf++)
                    mma_tf32(acc[mf][nf],
                             __float_as_uint(alo[mf].x), __float_as_uint(ahi[mf].x),
                             __float_as_uint(alo[mf].y), __float_as_uint(ahi[mf].y),
                             __float_as_uint(b0[nf]),    __float_as_uint(b1[nf]));
        }

        if (it < 63) {
            stage(buf ^ 1);
            __syncthreads();
            buf ^= 1;
        }
    }

    // Epilogue: warp's 64-col slice is within one 512-col block (64 | 512)
    const int wcol = colBase + wn * 64;
    const int dir  = wcol / 1536;
    const int cm   = wcol - dir * 1536;
    int btype = 0;
    const float* bptr = bias;
    if (cm >= 1024)      { btype = 2; bptr = bias + 1024 + dir * 512 + (cm - 1024); }
    else if (cm >= 512)  { btype = 1; bptr = bias + dir * 512 + (cm - 512); }

    #pragma unroll
    for (int nf = 0; nf < 8; nf++) {
        const int coff = nf * 8 + 2 * j;
        float bv0 = 0.f, bv1 = 0.f;
        if (btype) { bv0 = bptr[coff]; bv1 = bptr[coff + 1]; }
        const int col = wcol + coff;
        #pragma unroll
        for (int mf = 0; mf < 4; mf++) {
            const int row0 = rowBase + wm * 64 + mf * 16 + q;
            float v0 = acc[mf][nf][0], v1 = acc[mf][nf][1];
            float v2 = acc[mf][nf][2], v3 = acc[mf][nf][3];
            if (btype) {
                v0 = 1.f / (1.f + __expf(-(v0 + bv0)));
                v1 = 1.f / (1.f + __expf(-(v1 + bv1)));
                v2 = 1.f / (1.f + __expf(-(v2 + bv0)));
                v3 = 1.f / (1.f + __expf(-(v3 + bv1)));
            }
            *reinterpret_cast<float2*>(&U[(size_t)row0 * NDIM + col])
                = make_float2(v0, v1);
            *reinterpret_cast<float2*>(&U[(size_t)(row0 + 8) * NDIM + col])
                = make_float2(v2, v3);
        }
    }
}

// ---------------------------------------------------------------------------
// Chunked SRU scan (3-pass). Chain = dir*8192 + b*512 + i. Chunk g covers
// l in [g*64, g*64+64); dir1 traverses high->low within chunk & across chunks.
// ---------------------------------------------------------------------------
__global__ void scan1_kernel(const float* __restrict__ U,
                             float* __restrict__ Fo, float* __restrict__ Co) {
    const int idx = blockIdx.x * blockDim.x + threadIdx.x;   // 0..NCH*NCHAIN-1
    const int chain = idx & (NCHAIN - 1);
    const int g = idx >> 14;
    const int dir = chain >> 13;
    const int b = (chain >> 9) & 15;
    const int i = chain & 511;

    const float* u0 = U + (size_t)b * NDIM + dir * 1536 + i;
    const int ustep = BATCH * NDIM;

    float F = 1.f, C = 0.f;
    const int l0 = g * CH;
    if (dir == 0) {
        #pragma unroll 8
        for (int t = 0; t < CH; t++) {
            const float* up = u0 + (size_t)(l0 + t) * ustep;
            float xt = __ldg(up);
            float f  = __ldg(up + 512);
            C = f * C + (1.f - f) * xt;
            F *= f;
        }
    } else {
        #pragma unroll 8
        for (int t = 0; t < CH; t++) {
            const float* up = u0 + (size_t)(l0 + CH - 1 - t) * ustep;
            float xt = __ldg(up);
            float f  = __ldg(up + 512);
            C = f * C + (1.f - f) * xt;
            F *= f;
        }
    }
    Fo[idx] = F;
    Co[idx] = C;
}

__global__ void scan2_kernel(const float* __restrict__ Fo, const float* __restrict__ Co,
                             float* __restrict__ ce, float* __restrict__ Cout) {
    const int chain = blockIdx.x * blockDim.x + threadIdx.x;   // 0..16383
    const int dir = chain >> 13;
    const int b = (chain >> 9) & 15;
    const int i = chain & 511;

    float c = 0.f;
    #pragma unroll
    for (int t = 0; t < NCH; t++) {
        int g = dir ? (NCH - 1 - t) : t;
        ce[g * NCHAIN + chain] = c;
        c = Fo[g * NCHAIN + chain] * c + Co[g * NCHAIN + chain];
    }
    Cout[b * 1024 + dir * 512 + i] = c;
}

__global__ void scan3_kernel(const float* __restrict__ U,
                             const float* __restrict__ Xin,
                             const float* __restrict__ ce,
                             float* __restrict__ Xout,
                             float* __restrict__ XoutA) {   // tf32 copy or null
    const int idx = blockIdx.x * blockDim.x + threadIdx.x;
    const int chain = idx & (NCHAIN - 1);
    const int g = idx >> 14;
    const int dir = chain >> 13;
    const int b = (chain >> 9) & 15;
    const int i = chain & 511;

    const float* u0 = U   + (size_t)b * NDIM + dir * 1536 + i;
    const float* x0 = Xin + (size_t)b * DIN  + dir * 512  + i;
    const size_t hoff = (size_t)b * DIN + dir * 512 + i;
    const int ustep = BATCH * NDIM;
    const int xstep = BATCH * DIN;

    float c = ce[g * NCHAIN + chain];
    const int l0 = g * CH;
    #pragma unroll 4
    for (int t = 0; t < CH; t++) {
        const int l = dir ? (l0 + CH - 1 - t) : (l0 + t);
        const float* up = u0 + (size_t)l * ustep;
        float xt = __ldg(up);
        float f  = __ldg(up + 512);
        float r  = __ldg(up + 1024);
        float xp = __ldg(x0 + (size_t)l * xstep);
        c = f * c + (1.f - f) * xt;
        float h = r * tanh_fast(c) + (1.f - r) * xp;
        Xout[(size_t)l * xstep + hoff] = h;
        if (XoutA)
            XoutA[(size_t)l * xstep + hoff] = __uint_as_float(f2tf32(h));
    }
}

// ---------------------------------------------------------------------------
// Launch
// ---------------------------------------------------------------------------
extern "C" void kernel_launch(void* const* d_in, const int* in_sizes, int n_in,
                              void* d_out, int out_size) {
    const int*   tok = (const int*)d_in[0];
    const float* emb = (const float*)d_in[2];
    const float* Ws  = (const float*)d_in[3];
    const float* bs  = (const float*)d_in[4];
    float* out = (float*)d_out;

    float *x0, *x1, *xa, *u, *wt, *gF, *gC, *gce;
    cudaGetSymbolAddress((void**)&x0, g_x0);
    cudaGetSymbolAddress((void**)&x1, g_x1);
    cudaGetSymbolAddress((void**)&xa, g_xa);
    cudaGetSymbolAddress((void**)&u,  g_u);
    cudaGetSymbolAddress((void**)&wt, g_wt);
    cudaGetSymbolAddress((void**)&gF, g_F);
    cudaGetSymbolAddress((void**)&gC, g_C);
    cudaGetSymbolAddress((void**)&gce, g_ce);

    // Pre-convert all weights to tf32
    wconv_kernel<<<(NLAY * KDIM * NDIM / 4) / 256, 256>>>(Ws, wt);

    // Embedding gather (fp32 + tf32 copy)
    gather_kernel<<<(MROWS * DIN / 4) / 256, 256>>>(tok, emb, x0, xa);

    float* xcur = x0;
    float* xalt = x1;
    float* xout_base = out;
    float* hid_base  = out + (size_t)MROWS * DIN;

    dim3 ggrid(NDIM / 128, MROWS / 128);   // (24, 128)
    const int scan_blocks = (NCH * NCHAIN) / 256;  // 1024

    for (int l = 0; l < NLAY; l++) {
        const float* Wl = wt + (size_t)l * KDIM * NDIM;
        const float* bl = bs + (size_t)l * 2048;
        gemm_tf32_kernel<<<ggrid, 128>>>(xa, Wl, bl, u);

        float* xnext = (l == NLAY - 1) ? xout_base : xalt;
        float* xnextA = (l == NLAY - 1) ? nullptr : xa;
        float* cout_l = hid_base + (size_t)l * BATCH * DIN;

        scan1_kernel<<<scan_blocks, 256>>>(u, gF, gC);
        scan2_kernel<<<NCHAIN / 256, 256>>>(gF, gC, gce, cout_l);
        scan3_kernel<<<scan_blocks, 256>>>(u, xcur, gce, xnext, xnextA);

        xalt = xcur;
        xcur = xnext;
    }
}

// round 5
// speedup vs baseline: 1.6388x; 1.6388x over previous
#include <cuda_runtime.h>
#include <cuda_bf16.h>

// Problem constants
#define LSEQ  1024
#define BATCH 16
#define DIN   1024
#define NOUT  512
#define NLAY  4
#define MROWS (LSEQ*BATCH)   // 16384
#define KDIM  1024
#define NDIM  3072           // 6 * NOUT
#define NCH   16             // scan chunks
#define CH    64             // steps per chunk
#define NCHAIN 16384         // 2*B*NOUT

// Scratch (device globals: allocation-free)
__device__ float g_x0[MROWS * DIN];        // fp32 x (ping)
__device__ float g_x1[MROWS * DIN];        // fp32 x (pong)
__device__ float g_xa[MROWS * DIN];        // tf32 copy of GEMM A operand
__device__ float g_u [MROWS * NDIM];       // gate activations
__device__ float g_wt[NLAY * KDIM * NDIM]; // tf32-converted weights
__device__ float g_F [NCH * NCHAIN];       // chunk decay products
__device__ float g_C [NCH * NCHAIN];       // chunk affine constants
__device__ float g_ce[NCH * NCHAIN];       // chunk entry c values

__device__ __forceinline__ unsigned f2tf32(float x) {
    unsigned r;
    asm("cvt.rna.tf32.f32 %0, %1;" : "=r"(r) : "f"(x));
    return r;
}
__device__ __forceinline__ float tanh_fast(float x) {
    float y;
    asm("tanh.approx.f32 %0, %1;" : "=f"(y) : "f"(x));
    return y;
}
__device__ __forceinline__ void mma_tf32(float c[4],
                                         unsigned a0, unsigned a1, unsigned a2, unsigned a3,
                                         unsigned b0, unsigned b1) {
    asm volatile(
        "mma.sync.aligned.m16n8k8.row.col.f32.tf32.tf32.f32 "
        "{%0,%1,%2,%3}, {%4,%5,%6,%7}, {%8,%9}, {%0,%1,%2,%3};"
        : "+f"(c[0]), "+f"(c[1]), "+f"(c[2]), "+f"(c[3])
        : "r"(a0), "r"(a1), "r"(a2), "r"(a3), "r"(b0), "r"(b1));
}

// ---------------------------------------------------------------------------
// Weight pre-convert: fp32 -> tf32 (stored as float), once per run
// ---------------------------------------------------------------------------
__global__ void wconv_kernel(const float* __restrict__ W, float* __restrict__ Wt) {
    int e = blockIdx.x * blockDim.x + threadIdx.x;
    float4 v = reinterpret_cast<const float4*>(W)[e];
    v.x = __uint_as_float(f2tf32(v.x));
    v.y = __uint_as_float(f2tf32(v.y));
    v.z = __uint_as_float(f2tf32(v.z));
    v.w = __uint_as_float(f2tf32(v.w));
    reinterpret_cast<float4*>(Wt)[e] = v;
}

// ---------------------------------------------------------------------------
// Embedding gather: fp32 x + tf32 copy for GEMM A
// ---------------------------------------------------------------------------
__global__ void gather_kernel(const int* __restrict__ tok,
                              const float* __restrict__ emb,
                              float* __restrict__ out,
                              float* __restrict__ outA) {
    int e = blockIdx.x * blockDim.x + threadIdx.x;
    int row = e >> 8;
    int d4  = e & 255;
    int t = tok[row];
    float4 v = reinterpret_cast<const float4*>(emb + (size_t)t * DIN)[d4];
    reinterpret_cast<float4*>(out)[e] = v;
    v.x = __uint_as_float(f2tf32(v.x));
    v.y = __uint_as_float(f2tf32(v.y));
    v.z = __uint_as_float(f2tf32(v.z));
    v.w = __uint_as_float(f2tf32(v.w));
    reinterpret_cast<float4*>(outA)[e] = v;
}

// ---------------------------------------------------------------------------
// TF32 GEMM (round-3 shape, cvt-free): U = X(M,K)*W(K,N).
// Block 128x128, BK=16, 256 threads (8 warps as 2x4, warp tile 64x32).
// Inputs already tf32-rounded. Double-buffered smem, register prefetch,
// all-float4 staging. Fused bias+sigmoid on gate columns.
//  A smem pair layout per kstep plane s:
//     As[s*1032 + row*8] = {k0,k4,k1,k5}, +4 = {k2,k6,k3,k7}  (k rel. 8s)
//  B smem plain [k][n], row stride 136 (conflict-free)
// ---------------------------------------------------------------------------
#define A_PLANE 1032
#define B_STRIDE 136

__global__ void __launch_bounds__(256)
gemm_tf32_kernel(const float* __restrict__ A,
                 const float* __restrict__ W,
                 const float* __restrict__ bias,
                 float* __restrict__ U) {
    __shared__ float As[2][2 * A_PLANE];     // 16.5 KB
    __shared__ float Bs[2][16 * B_STRIDE];   // 17.4 KB

    const int tid  = threadIdx.x;
    const int lane = tid & 31;
    const int warp = tid >> 5;
    const int wm = warp >> 2;        // 0..1
    const int wn = warp & 3;         // 0..3
    const int rowBase = blockIdx.y * 128;
    const int colBase = blockIdx.x * 128;

    // A staging: row = tid>>1 (0..127), k-half = (tid&1)*8 (one kstep plane)
    const int ar = tid >> 1;
    const int ah = tid & 1;          // plane s
    const float* Ag = A + (size_t)(rowBase + ar) * KDIM + ah * 8;
    // B staging: k = tid>>4 (0..15), n = (tid&15)*4 (+64 for e=1)
    const int bk = tid >> 4;
    const int bn = (tid & 15) * 4;
    const float* Bg = W + (size_t)bk * NDIM + colBase + bn;

    float4 pa0, pa1, pb0, pb1;
    pa0 = *reinterpret_cast<const float4*>(Ag);
    pa1 = *reinterpret_cast<const float4*>(Ag + 4);
    pb0 = *reinterpret_cast<const float4*>(Bg);
    pb1 = *reinterpret_cast<const float4*>(Bg + 64);

    float acc[4][4][4];
    #pragma unroll
    for (int mf = 0; mf < 4; mf++)
        #pragma unroll
        for (int nf = 0; nf < 4; nf++)
            #pragma unroll
            for (int e = 0; e < 4; e++) acc[mf][nf][e] = 0.f;

    auto stage = [&](int buf) {
        float* ap = &As[buf][ah * A_PLANE + ar * 8];
        *reinterpret_cast<float4*>(ap)     = make_float4(pa0.x, pa1.x, pa0.y, pa1.y);
        *reinterpret_cast<float4*>(ap + 4) = make_float4(pa0.z, pa1.z, pa0.w, pa1.w);
        float* bp = &Bs[buf][bk * B_STRIDE + bn];
        *reinterpret_cast<float4*>(bp)      = pb0;
        *reinterpret_cast<float4*>(bp + 64) = pb1;
    };

    stage(0);
    __syncthreads();

    const int q = lane >> 2;     // 0..7
    const int j = lane & 3;      // 0..3
    int buf = 0;

    for (int it = 0; it < 64; it++) {
        if (it < 63) {
            const float* Ag2 = Ag + (it + 1) * 16;
            const float* Bg2 = Bg + (size_t)(it + 1) * 16 * NDIM;
            pa0 = *reinterpret_cast<const float4*>(Ag2);
            pa1 = *reinterpret_cast<const float4*>(Ag2 + 4);
            pb0 = *reinterpret_cast<const float4*>(Bg2);
            pb1 = *reinterpret_cast<const float4*>(Bg2 + 64);
        }

        #pragma unroll
        for (int s = 0; s < 2; s++) {
            float2 alo[4], ahi[4];
            #pragma unroll
            for (int mf = 0; mf < 4; mf++) {
                int r = wm * 64 + mf * 16 + q;
                alo[mf] = *reinterpret_cast<const float2*>(
                    &As[buf][s * A_PLANE + r * 8 + j * 2]);
                ahi[mf] = *reinterpret_cast<const float2*>(
                    &As[buf][s * A_PLANE + (r + 8) * 8 + j * 2]);
            }
            float b0[4], b1[4];
            #pragma unroll
            for (int nf = 0; nf < 4; nf++) {
                int n = wn * 32 + nf * 8 + q;
                b0[nf] = Bs[buf][(s * 8 + j) * B_STRIDE + n];
                b1[nf] = Bs[buf][(s * 8 + j + 4) * B_STRIDE + n];
            }
            #pragma unroll
            for (int mf = 0; mf < 4; mf++)
                #pragma unroll
                for (int nf = 0; nf < 4; nf++)
                    mma_tf32(acc[mf][nf],
                             __float_as_uint(alo[mf].x), __float_as_uint(ahi[mf].x),
                             __float_as_uint(alo[mf].y), __float_as_uint(ahi[mf].y),
                             __float_as_uint(b0[nf]),    __float_as_uint(b1[nf]));
        }

        if (it < 63) {
            stage(buf ^ 1);
            __syncthreads();
            buf ^= 1;
        }
    }

    // Epilogue: warp's 32-col slice lies within one 512-col block
    const int wcol = colBase + wn * 32;
    const int dir  = wcol / 1536;
    const int cm   = wcol - dir * 1536;
    int btype = 0;
    const float* bptr = bias;
    if (cm >= 1024)      { btype = 2; bptr = bias + 1024 + dir * 512 + (cm - 1024); }
    else if (cm >= 512)  { btype = 1; bptr = bias + dir * 512 + (cm - 512); }

    #pragma unroll
    for (int nf = 0; nf < 4; nf++) {
        const int coff = nf * 8 + 2 * j;
        float bv0 = 0.f, bv1 = 0.f;
        if (btype) { bv0 = bptr[coff]; bv1 = bptr[coff + 1]; }
        const int col = wcol + coff;
        #pragma unroll
        for (int mf = 0; mf < 4; mf++) {
            const int row0 = rowBase + wm * 64 + mf * 16 + q;
            float v0 = acc[mf][nf][0], v1 = acc[mf][nf][1];
            float v2 = acc[mf][nf][2], v3 = acc[mf][nf][3];
            if (btype) {
                v0 = 1.f / (1.f + __expf(-(v0 + bv0)));
                v1 = 1.f / (1.f + __expf(-(v1 + bv1)));
                v2 = 1.f / (1.f + __expf(-(v2 + bv0)));
                v3 = 1.f / (1.f + __expf(-(v3 + bv1)));
            }
            *reinterpret_cast<float2*>(&U[(size_t)row0 * NDIM + col])
                = make_float2(v0, v1);
            *reinterpret_cast<float2*>(&U[(size_t)(row0 + 8) * NDIM + col])
                = make_float2(v2, v3);
        }
    }
}

// ---------------------------------------------------------------------------
// Chunked SRU scan (3-pass). Chain = dir*8192 + b*512 + i.
// ---------------------------------------------------------------------------
__global__ void scan1_kernel(const float* __restrict__ U,
                             float* __restrict__ Fo, float* __restrict__ Co) {
    const int idx = blockIdx.x * blockDim.x + threadIdx.x;
    const int chain = idx & (NCHAIN - 1);
    const int g = idx >> 14;
    const int dir = chain >> 13;
    const int b = (chain >> 9) & 15;
    const int i = chain & 511;

    const float* u0 = U + (size_t)b * NDIM + dir * 1536 + i;
    const int ustep = BATCH * NDIM;

    float F = 1.f, C = 0.f;
    const int l0 = g * CH;
    if (dir == 0) {
        #pragma unroll 8
        for (int t = 0; t < CH; t++) {
            const float* up = u0 + (size_t)(l0 + t) * ustep;
            float xt = __ldg(up);
            float f  = __ldg(up + 512);
            C = f * C + (1.f - f) * xt;
            F *= f;
        }
    } else {
        #pragma unroll 8
        for (int t = 0; t < CH; t++) {
            const float* up = u0 + (size_t)(l0 + CH - 1 - t) * ustep;
            float xt = __ldg(up);
            float f  = __ldg(up + 512);
            C = f * C + (1.f - f) * xt;
            F *= f;
        }
    }
    Fo[idx] = F;
    Co[idx] = C;
}

__global__ void scan2_kernel(const float* __restrict__ Fo, const float* __restrict__ Co,
                             float* __restrict__ ce, float* __restrict__ Cout) {
    const int chain = blockIdx.x * blockDim.x + threadIdx.x;
    const int dir = chain >> 13;
    const int b = (chain >> 9) & 15;
    const int i = chain & 511;

    float c = 0.f;
    #pragma unroll
    for (int t = 0; t < NCH; t++) {
        int g = dir ? (NCH - 1 - t) : t;
        ce[g * NCHAIN + chain] = c;
        c = Fo[g * NCHAIN + chain] * c + Co[g * NCHAIN + chain];
    }
    Cout[b * 1024 + dir * 512 + i] = c;
}

__global__ void scan3_kernel(const float* __restrict__ U,
                             const float* __restrict__ Xin,
                             const float* __restrict__ ce,
                             float* __restrict__ Xout,
                             float* __restrict__ XoutA) {   // tf32 copy or null
    const int idx = blockIdx.x * blockDim.x + threadIdx.x;
    const int chain = idx & (NCHAIN - 1);
    const int g = idx >> 14;
    const int dir = chain >> 13;
    const int b = (chain >> 9) & 15;
    const int i = chain & 511;

    const float* u0 = U   + (size_t)b * NDIM + dir * 1536 + i;
    const float* x0 = Xin + (size_t)b * DIN  + dir * 512  + i;
    const size_t hoff = (size_t)b * DIN + dir * 512 + i;
    const int ustep = BATCH * NDIM;
    const int xstep = BATCH * DIN;

    float c = ce[g * NCHAIN + chain];
    const int l0 = g * CH;
    #pragma unroll 4
    for (int t = 0; t < CH; t++) {
        const int l = dir ? (l0 + CH - 1 - t) : (l0 + t);
        const float* up = u0 + (size_t)l * ustep;
        float xt = __ldg(up);
        float f  = __ldg(up + 512);
        float r  = __ldg(up + 1024);
        float xp = __ldg(x0 + (size_t)l * xstep);
        c = f * c + (1.f - f) * xt;
        float h = r * tanh_fast(c) + (1.f - r) * xp;
        Xout[(size_t)l * xstep + hoff] = h;
        if (XoutA)
            XoutA[(size_t)l * xstep + hoff] = __uint_as_float(f2tf32(h));
    }
}

// ---------------------------------------------------------------------------
// Launch
// ---------------------------------------------------------------------------
extern "C" void kernel_launch(void* const* d_in, const int* in_sizes, int n_in,
                              void* d_out, int out_size) {
    const int*   tok = (const int*)d_in[0];
    const float* emb = (const float*)d_in[2];
    const float* Ws  = (const float*)d_in[3];
    const float* bs  = (const float*)d_in[4];
    float* out = (float*)d_out;

    float *x0, *x1, *xa, *u, *wt, *gF, *gC, *gce;
    cudaGetSymbolAddress((void**)&x0, g_x0);
    cudaGetSymbolAddress((void**)&x1, g_x1);
    cudaGetSymbolAddress((void**)&xa, g_xa);
    cudaGetSymbolAddress((void**)&u,  g_u);
    cudaGetSymbolAddress((void**)&wt, g_wt);
    cudaGetSymbolAddress((void**)&gF, g_F);
    cudaGetSymbolAddress((void**)&gC, g_C);
    cudaGetSymbolAddress((void**)&gce, g_ce);

    // Pre-convert all weights to tf32
    wconv_kernel<<<(NLAY * KDIM * NDIM / 4) / 256, 256>>>(Ws, wt);

    // Embedding gather (fp32 + tf32 copy)
    gather_kernel<<<(MROWS * DIN / 4) / 256, 256>>>(tok, emb, x0, xa);

    float* xcur = x0;
    float* xalt = x1;
    float* xout_base = out;
    float* hid_base  = out + (size_t)MROWS * DIN;

    dim3 ggrid(NDIM / 128, MROWS / 128);   // (24, 128)
    const int scan_blocks = (NCH * NCHAIN) / 256;  // 1024

    for (int l = 0; l < NLAY; l++) {
        const float* Wl = wt + (size_t)l * KDIM * NDIM;
        const float* bl = bs + (size_t)l * 2048;
        gemm_tf32_kernel<<<ggrid, 256>>>(xa, Wl, bl, u);

        float* xnext = (l == NLAY - 1) ? xout_base : xalt;
        float* xnextA = (l == NLAY - 1) ? nullptr : xa;
        float* cout_l = hid_base + (size_t)l * BATCH * DIN;

        scan1_kernel<<<scan_blocks, 256>>>(u, gF, gC);
        scan2_kernel<<<NCHAIN / 256, 256>>>(gF, gC, gce, cout_l);
        scan3_kernel<<<scan_blocks, 256>>>(u, xcur, gce, xnext, xnextA);

        xalt = xcur;
        xcur = xnext;
    }
}

// round 6
// speedup vs baseline: 1.8075x; 1.1029x over previous
#include <cuda_runtime.h>
#include <cuda_bf16.h>

// Problem constants
#define LSEQ  1024
#define BATCH 16
#define DIN   1024
#define NOUT  512
#define NLAY  4
#define MROWS (LSEQ*BATCH)   // 16384
#define KDIM  1024
#define NDIM  3072           // 6 * NOUT
#define NCH   16             // scan chunks
#define CH    64             // steps per chunk
#define NCHAIN 16384         // 2*B*NOUT

// Scratch (device globals: allocation-free)
__device__ float g_x0[MROWS * DIN];        // x (tf32-valued) ping
__device__ float g_x1[MROWS * DIN];        // x (tf32-valued) pong
__device__ float g_u [MROWS * NDIM];       // gate activations
__device__ float g_wt[NLAY * KDIM * NDIM]; // tf32-converted weights
__device__ float g_F [NCH * NCHAIN];       // chunk decay products
__device__ float g_C [NCH * NCHAIN];       // chunk affine constants
__device__ float g_ce[NCH * NCHAIN];       // chunk entry c values

__device__ __forceinline__ unsigned f2tf32(float x) {
    unsigned r;
    asm("cvt.rna.tf32.f32 %0, %1;" : "=r"(r) : "f"(x));
    return r;
}
__device__ __forceinline__ float tanh_fast(float x) {
    float y;
    asm("tanh.approx.f32 %0, %1;" : "=f"(y) : "f"(x));
    return y;
}
__device__ __forceinline__ void mma_tf32(float c[4],
                                         unsigned a0, unsigned a1, unsigned a2, unsigned a3,
                                         unsigned b0, unsigned b1) {
    asm volatile(
        "mma.sync.aligned.m16n8k8.row.col.f32.tf32.tf32.f32 "
        "{%0,%1,%2,%3}, {%4,%5,%6,%7}, {%8,%9}, {%0,%1,%2,%3};"
        : "+f"(c[0]), "+f"(c[1]), "+f"(c[2]), "+f"(c[3])
        : "r"(a0), "r"(a1), "r"(a2), "r"(a3), "r"(b0), "r"(b1));
}

// ---------------------------------------------------------------------------
// Weight pre-convert fp32 -> tf32 (once)
// ---------------------------------------------------------------------------
__global__ void wconv_kernel(const float* __restrict__ W, float* __restrict__ Wt) {
    int e = blockIdx.x * blockDim.x + threadIdx.x;
    float4 v = reinterpret_cast<const float4*>(W)[e];
    v.x = __uint_as_float(f2tf32(v.x));
    v.y = __uint_as_float(f2tf32(v.y));
    v.z = __uint_as_float(f2tf32(v.z));
    v.w = __uint_as_float(f2tf32(v.w));
    reinterpret_cast<float4*>(Wt)[e] = v;
}

// ---------------------------------------------------------------------------
// Embedding gather -> tf32-rounded x
// ---------------------------------------------------------------------------
__global__ void gather_kernel(const int* __restrict__ tok,
                              const float* __restrict__ emb,
                              float* __restrict__ out) {
    int e = blockIdx.x * blockDim.x + threadIdx.x;
    int row = e >> 8;
    int d4  = e & 255;
    int t = tok[row];
    float4 v = reinterpret_cast<const float4*>(emb + (size_t)t * DIN)[d4];
    v.x = __uint_as_float(f2tf32(v.x));
    v.y = __uint_as_float(f2tf32(v.y));
    v.z = __uint_as_float(f2tf32(v.z));
    v.w = __uint_as_float(f2tf32(v.w));
    reinterpret_cast<float4*>(out)[e] = v;
}

// ---------------------------------------------------------------------------
// TF32 GEMM: U = X(M,K)*W(K,N). Block tile 128x256, BK=16, 256 threads,
// 8 warps as 2x4 grid of 64x64 warp tiles. Inputs pre-rounded to tf32.
// Double-buffered dynamic smem (~49KB), fused bias+sigmoid epilogue.
//  A smem: pair layout, plane per kstep s (plane stride 1024, row stride 8):
//     As[s*1024 + row*8] = {k0,k4,k1,k5}, +4 = {k2,k6,k3,k7}
//  B smem: [k][n], row stride 264 (264 mod 32 == 8 -> conflict-free frags)
// ---------------------------------------------------------------------------
#define A_BUF   2048          // floats per buffer (2 planes x 1024)
#define B_STRIDE 264
#define B_BUF   (16 * B_STRIDE)   // 4224 floats
#define SMEM_FLOATS (2 * A_BUF + 2 * B_BUF)   // 12544 floats = 50176 B

__global__ void __launch_bounds__(256, 1)
gemm_tf32_kernel(const float* __restrict__ A,
                 const float* __restrict__ W,
                 const float* __restrict__ bias,
                 float* __restrict__ U) {
    extern __shared__ float sm[];
    float* Asm = sm;                    // 2 * A_BUF
    float* Bsm = sm + 2 * A_BUF;        // 2 * B_BUF

    const int tid  = threadIdx.x;
    const int lane = tid & 31;
    const int warp = tid >> 5;
    const int wm = warp >> 2;        // 0..1
    const int wn = warp & 3;         // 0..3
    const int rowBase = blockIdx.y * 128;
    const int colBase = blockIdx.x * 256;

    // A staging: row = tid>>1 (0..127), plane = tid&1
    const int ar = tid >> 1;
    const int ah = tid & 1;
    const float* Ag = A + (size_t)(rowBase + ar) * KDIM + ah * 8;
    // B staging: k = tid>>4 (0..15), n = (tid&15)*4 (+e*64)
    const int bk = tid >> 4;
    const int bn = (tid & 15) * 4;
    const float* Bg = W + (size_t)bk * NDIM + colBase + bn;

    float4 pa0, pa1, pb[4];
    pa0 = *reinterpret_cast<const float4*>(Ag);
    pa1 = *reinterpret_cast<const float4*>(Ag + 4);
    #pragma unroll
    for (int e = 0; e < 4; e++)
        pb[e] = *reinterpret_cast<const float4*>(Bg + e * 64);

    float acc[4][8][4];
    #pragma unroll
    for (int mf = 0; mf < 4; mf++)
        #pragma unroll
        for (int nf = 0; nf < 8; nf++)
            #pragma unroll
            for (int e = 0; e < 4; e++) acc[mf][nf][e] = 0.f;

    auto stage = [&](int buf) {
        float* ap = &Asm[buf * A_BUF + ah * 1024 + ar * 8];
        *reinterpret_cast<float4*>(ap)     = make_float4(pa0.x, pa1.x, pa0.y, pa1.y);
        *reinterpret_cast<float4*>(ap + 4) = make_float4(pa0.z, pa1.z, pa0.w, pa1.w);
        float* bp = &Bsm[buf * B_BUF + bk * B_STRIDE + bn];
        #pragma unroll
        for (int e = 0; e < 4; e++)
            *reinterpret_cast<float4*>(bp + e * 64) = pb[e];
    };

    stage(0);
    __syncthreads();

    const int q = lane >> 2;     // 0..7
    const int j = lane & 3;      // 0..3
    int buf = 0;

    for (int it = 0; it < 64; it++) {
        if (it < 63) {
            const float* Ag2 = Ag + (it + 1) * 16;
            const float* Bg2 = Bg + (size_t)(it + 1) * 16 * NDIM;
            pa0 = *reinterpret_cast<const float4*>(Ag2);
            pa1 = *reinterpret_cast<const float4*>(Ag2 + 4);
            #pragma unroll
            for (int e = 0; e < 4; e++)
                pb[e] = *reinterpret_cast<const float4*>(Bg2 + e * 64);
        }

        #pragma unroll
        for (int s = 0; s < 2; s++) {
            const float* ab = &Asm[buf * A_BUF + s * 1024];
            const float* bb = &Bsm[buf * B_BUF + (s * 8 + j) * B_STRIDE + wn * 64 + q];
            float2 alo[4], ahi[4];
            #pragma unroll
            for (int mf = 0; mf < 4; mf++) {
                int r = wm * 64 + mf * 16 + q;
                alo[mf] = *reinterpret_cast<const float2*>(ab + r * 8 + j * 2);
                ahi[mf] = *reinterpret_cast<const float2*>(ab + (r + 8) * 8 + j * 2);
            }
            float b0[8], b1[8];
            #pragma unroll
            for (int nf = 0; nf < 8; nf++) {
                b0[nf] = bb[nf * 8];
                b1[nf] = bb[4 * B_STRIDE + nf * 8];
            }
            #pragma unroll
            for (int mf = 0; mf < 4; mf++)
                #pragma unroll
                for (int nf = 0; nf < 8; nf++)
                    mma_tf32(acc[mf][nf],
                             __float_as_uint(alo[mf].x), __float_as_uint(ahi[mf].x),
                             __float_as_uint(alo[mf].y), __float_as_uint(ahi[mf].y),
                             __float_as_uint(b0[nf]),    __float_as_uint(b1[nf]));
        }

        if (it < 63) {
            stage(buf ^ 1);
            __syncthreads();
            buf ^= 1;
        }
    }

    // Epilogue: warp's 64-col slice lies within one 512-col block (64 | 512)
    const int wcol = colBase + wn * 64;
    const int dir  = wcol / 1536;
    const int cm   = wcol - dir * 1536;
    int btype = 0;
    const float* bptr = bias;
    if (cm >= 1024)      { btype = 2; bptr = bias + 1024 + dir * 512 + (cm - 1024); }
    else if (cm >= 512)  { btype = 1; bptr = bias + dir * 512 + (cm - 512); }

    #pragma unroll
    for (int nf = 0; nf < 8; nf++) {
        const int coff = nf * 8 + 2 * j;
        float bv0 = 0.f, bv1 = 0.f;
        if (btype) { bv0 = bptr[coff]; bv1 = bptr[coff + 1]; }
        const int col = wcol + coff;
        #pragma unroll
        for (int mf = 0; mf < 4; mf++) {
            const int row0 = rowBase + wm * 64 + mf * 16 + q;
            float v0 = acc[mf][nf][0], v1 = acc[mf][nf][1];
            float v2 = acc[mf][nf][2], v3 = acc[mf][nf][3];
            if (btype) {
                v0 = 1.f / (1.f + __expf(-(v0 + bv0)));
                v1 = 1.f / (1.f + __expf(-(v1 + bv1)));
                v2 = 1.f / (1.f + __expf(-(v2 + bv0)));
                v3 = 1.f / (1.f + __expf(-(v3 + bv1)));
            }
            *reinterpret_cast<float2*>(&U[(size_t)row0 * NDIM + col])
                = make_float2(v0, v1);
            *reinterpret_cast<float2*>(&U[(size_t)(row0 + 8) * NDIM + col])
                = make_float2(v2, v3);
        }
    }
}

// ---------------------------------------------------------------------------
// Chunked SRU scan (3-pass). Chain = dir*8192 + b*512 + i.
// ---------------------------------------------------------------------------
__global__ void scan1_kernel(const float* __restrict__ U,
                             float* __restrict__ Fo, float* __restrict__ Co) {
    const int idx = blockIdx.x * blockDim.x + threadIdx.x;
    const int chain = idx & (NCHAIN - 1);
    const int g = idx >> 14;
    const int dir = chain >> 13;
    const int b = (chain >> 9) & 15;
    const int i = chain & 511;

    const float* u0 = U + (size_t)b * NDIM + dir * 1536 + i;
    const int ustep = BATCH * NDIM;

    float F = 1.f, C = 0.f;
    const int l0 = g * CH;
    if (dir == 0) {
        #pragma unroll 8
        for (int t = 0; t < CH; t++) {
            const float* up = u0 + (size_t)(l0 + t) * ustep;
            float xt = __ldg(up);
            float f  = __ldg(up + 512);
            C = f * C + (1.f - f) * xt;
            F *= f;
        }
    } else {
        #pragma unroll 8
        for (int t = 0; t < CH; t++) {
            const float* up = u0 + (size_t)(l0 + CH - 1 - t) * ustep;
            float xt = __ldg(up);
            float f  = __ldg(up + 512);
            C = f * C + (1.f - f) * xt;
            F *= f;
        }
    }
    Fo[idx] = F;
    Co[idx] = C;
}

__global__ void scan2_kernel(const float* __restrict__ Fo, const float* __restrict__ Co,
                             float* __restrict__ ce, float* __restrict__ Cout) {
    const int chain = blockIdx.x * blockDim.x + threadIdx.x;
    const int dir = chain >> 13;
    const int b = (chain >> 9) & 15;
    const int i = chain & 511;

    float c = 0.f;
    #pragma unroll
    for (int t = 0; t < NCH; t++) {
        int g = dir ? (NCH - 1 - t) : t;
        ce[g * NCHAIN + chain] = c;
        c = Fo[g * NCHAIN + chain] * c + Co[g * NCHAIN + chain];
    }
    Cout[b * 1024 + dir * 512 + i] = c;
}

__global__ void scan3_kernel(const float* __restrict__ U,
                             const float* __restrict__ Xin,
                             const float* __restrict__ ce,
                             float* __restrict__ Xout,
                             int roundOut) {   // 1: round h to tf32 (feeds next GEMM)
    const int idx = blockIdx.x * blockDim.x + threadIdx.x;
    const int chain = idx & (NCHAIN - 1);
    const int g = idx >> 14;
    const int dir = chain >> 13;
    const int b = (chain >> 9) & 15;
    const int i = chain & 511;

    const float* u0 = U   + (size_t)b * NDIM + dir * 1536 + i;
    const float* x0 = Xin + (size_t)b * DIN  + dir * 512  + i;
    const size_t hoff = (size_t)b * DIN + dir * 512 + i;
    const int ustep = BATCH * NDIM;
    const int xstep = BATCH * DIN;

    float c = ce[g * NCHAIN + chain];
    const int l0 = g * CH;
    #pragma unroll 4
    for (int t = 0; t < CH; t++) {
        const int l = dir ? (l0 + CH - 1 - t) : (l0 + t);
        const float* up = u0 + (size_t)l * ustep;
        float xt = __ldg(up);
        float f  = __ldg(up + 512);
        float r  = __ldg(up + 1024);
        float xp = __ldg(x0 + (size_t)l * xstep);
        c = f * c + (1.f - f) * xt;
        float h = r * tanh_fast(c) + (1.f - r) * xp;
        if (roundOut) h = __uint_as_float(f2tf32(h));
        Xout[(size_t)l * xstep + hoff] = h;
    }
}

// ---------------------------------------------------------------------------
// Launch
// ---------------------------------------------------------------------------
extern "C" void kernel_launch(void* const* d_in, const int* in_sizes, int n_in,
                              void* d_out, int out_size) {
    const int*   tok = (const int*)d_in[0];
    const float* emb = (const float*)d_in[2];
    const float* Ws  = (const float*)d_in[3];
    const float* bs  = (const float*)d_in[4];
    float* out = (float*)d_out;

    float *x0, *x1, *u, *wt, *gF, *gC, *gce;
    cudaGetSymbolAddress((void**)&x0, g_x0);
    cudaGetSymbolAddress((void**)&x1, g_x1);
    cudaGetSymbolAddress((void**)&u,  g_u);
    cudaGetSymbolAddress((void**)&wt, g_wt);
    cudaGetSymbolAddress((void**)&gF, g_F);
    cudaGetSymbolAddress((void**)&gC, g_C);
    cudaGetSymbolAddress((void**)&gce, g_ce);

    const int smemBytes = SMEM_FLOATS * 4;   // 50176
    cudaFuncSetAttribute(gemm_tf32_kernel,
                         cudaFuncAttributeMaxDynamicSharedMemorySize, smemBytes);

    // Pre-convert all weights to tf32
    wconv_kernel<<<(NLAY * KDIM * NDIM / 4) / 256, 256>>>(Ws, wt);

    // Embedding gather (tf32-rounded x)
    gather_kernel<<<(MROWS * DIN / 4) / 256, 256>>>(tok, emb, x0);

    float* xcur = x0;
    float* xalt = x1;
    float* hid_base = out + (size_t)MROWS * DIN;

    dim3 ggrid(NDIM / 256, MROWS / 128);   // (12, 128)
    const int scan_blocks = (NCH * NCHAIN) / 256;  // 1024

    for (int l = 0; l < NLAY; l++) {
        const float* Wl = wt + (size_t)l * KDIM * NDIM;
        const float* bl = bs + (size_t)l * 2048;
        gemm_tf32_kernel<<<ggrid, 256, smemBytes>>>(xcur, Wl, bl, u);

        float* xnext = (l == NLAY - 1) ? out : xalt;
        int roundNext = (l == NLAY - 1) ? 0 : 1;
        float* cout_l = hid_base + (size_t)l * BATCH * DIN;

        scan1_kernel<<<scan_blocks, 256>>>(u, gF, gC);
        scan2_kernel<<<NCHAIN / 256, 256>>>(gF, gC, gce, cout_l);
        scan3_kernel<<<scan_blocks, 256>>>(u, xcur, gce, xnext, roundNext);

        xalt = xcur;
        xcur = xnext;
    }
}